// round 16
// baseline (speedup 1.0000x reference)
#include <cuda_runtime.h>
#include <cuda_bf16.h>
#include <math.h>
#include <stdint.h>

#define Dn 4096
#define Bn 32
#define Un 64

__device__ __nv_bfloat16 g_xsp[2][64][Dn];
__device__ __nv_bfloat16 g_csp[2][64][Dn];
__device__ float g_fpart[8][2][Bn][Dn];
__device__ float g_act[2][Bn * Dn];
__device__ float g_mp1[64][Bn][512];
__device__ float g_o[Bn * Un];
__device__ float g_dm[Dn];
__device__ float g_part[2][64][Dn];
__device__ float g_sinv[2][Dn];

__device__ __forceinline__ uint32_t smem_u32(const void* p) {
    uint32_t a;
    asm("{ .reg .u64 t; cvta.to.shared.u64 t, %1; cvt.u32.u64 %0, t; }" : "=r"(a) : "l"(p));
    return a;
}
__device__ __forceinline__ void cvt2(float f0, float f1, uint32_t& h, uint32_t& l) {
    asm("cvt.rn.bf16x2.f32 %0, %1, %2;" : "=r"(h) : "f"(f1), "f"(f0));
    float g0 = __uint_as_float(h << 16);
    float g1 = __uint_as_float(h & 0xFFFF0000u);
    asm("cvt.rn.bf16x2.f32 %0, %1, %2;" : "=r"(l) : "f"(f1 - g1), "f"(f0 - g0));
}
__device__ __forceinline__ void mma16816(float* d, const uint32_t* a,
                                         uint32_t b0, uint32_t b1) {
    asm volatile(
        "mma.sync.aligned.m16n8k16.row.col.f32.bf16.bf16.f32 "
        "{%0,%1,%2,%3}, {%4,%5,%6,%7}, {%8,%9}, {%0,%1,%2,%3};"
        : "+f"(d[0]), "+f"(d[1]), "+f"(d[2]), "+f"(d[3])
        : "r"(a[0]), "r"(a[1]), "r"(a[2]), "r"(a[3]), "r"(b0), "r"(b1));
}
#define LDSM_X4(r, p) \
    asm volatile("ldmatrix.sync.aligned.m8n8.x4.shared.b16 {%0,%1,%2,%3}, [%4];" \
        : "=r"((r)[0]), "=r"((r)[1]), "=r"((r)[2]), "=r"((r)[3]) : "r"(p))
#define LDSM_X4T(r, p) \
    asm volatile("ldmatrix.sync.aligned.m8n8.x4.trans.shared.b16 {%0,%1,%2,%3}, [%4];" \
        : "=r"((r)[0]), "=r"((r)[1]), "=r"((r)[2]), "=r"((r)[3]) : "r"(p))
#define CP_ASYNC16(dst, src) \
    asm volatile("cp.async.ca.shared.global [%0], [%1], 16;" :: "r"(dst), "l"(src))
#define CP_COMMIT() asm volatile("cp.async.commit_group;" ::: "memory")
#define CP_WAIT(n)  asm volatile("cp.async.wait_group %0;" :: "n"(n) : "memory")

// ---------------------------------------------------------------------------
__global__ __launch_bounds__(256) void prep_all(
    const float* __restrict__ stim, const float* __restrict__ prev,
    const float* __restrict__ decay)
{
    int mat = blockIdx.y;
    const float* X = mat ? prev : stim;
    int idx = blockIdx.x * 256 + threadIdx.x;
    float x = X[idx];
    __nv_bfloat16 hi = __float2bfloat16(x);
    __nv_bfloat16 lo = __float2bfloat16(x - __bfloat162float(hi));
    int b = idx >> 12, d = idx & 4095;
    g_xsp[mat][b][d] = hi;
    g_xsp[mat][b + 32][d] = lo;
    if (mat == 0 && idx < Dn) g_dm[idx] = 1.0f - decay[idx];
}

// ---------------------------------------------------------------------------
__global__ __launch_bounds__(128) void fwd_mma3(
    const float* __restrict__ Wh, const float* __restrict__ Wr)
{
    const int mat = blockIdx.z;
    const float* __restrict__ W = mat ? Wr : Wh;
    const int n0 = blockIdx.x * 64;
    const int kbase = blockIdx.y * 512;

    __shared__ __nv_bfloat16 As[2][64][40];
    __shared__ __nv_bfloat16 Bh[32][72];
    __shared__ __nv_bfloat16 Bl[32][72];

    const int tid = threadIdx.x;
    const int lane = tid & 31;
    const int wid = tid >> 5;
    const int nloc = wid << 4;

    const int lsub = lane >> 3;
    const int arow = (lane & 7) + ((lsub & 1) << 3);
    const int acol = (lsub & 2) << 2;
    const int brow = (lane & 7) + ((lane & 8) ? 8 : 0);
    const int bcol = nloc + ((lane & 16) ? 8 : 0);

    const int ar0 = tid >> 1;
    const int as0 = (tid & 1) << 1;

    float d[4][2][4] = {};
    float4 wreg[4];

    {
        #pragma unroll
        for (int r = 0; r < 2; ++r) {
            int seg = as0 + r;
            CP_ASYNC16(smem_u32(&As[0][ar0][seg * 8]),
                       (const void*)&g_xsp[mat][ar0][kbase + seg * 8]);
        }
        CP_COMMIT();
        #pragma unroll
        for (int r = 0; r < 4; ++r) {
            int idx = tid + r * 128;
            wreg[r] = *(const float4*)&W[(size_t)(kbase + (idx >> 4)) * Dn + n0 + (idx & 15) * 4];
        }
    }

    for (int c = 0; c < 16; ++c) {
        const int buf = c & 1;
        #pragma unroll
        for (int r = 0; r < 4; ++r) {
            int idx = tid + r * 128;
            int row = idx >> 4, col = (idx & 15) * 4;
            float4 w = wreg[r];
            uint32_t h0, l0, h1, l1;
            cvt2(w.x, w.y, h0, l0);
            cvt2(w.z, w.w, h1, l1);
            asm volatile("st.shared.v2.b32 [%0], {%1,%2};"
                :: "r"(smem_u32(&Bh[row][col])), "r"(h0), "r"(h1) : "memory");
            asm volatile("st.shared.v2.b32 [%0], {%1,%2};"
                :: "r"(smem_u32(&Bl[row][col])), "r"(l0), "r"(l1) : "memory");
        }
        if (c < 15) {
            const int k1 = kbase + (c + 1) * 32;
            #pragma unroll
            for (int r = 0; r < 2; ++r) {
                int seg = as0 + r;
                CP_ASYNC16(smem_u32(&As[buf ^ 1][ar0][seg * 8]),
                           (const void*)&g_xsp[mat][ar0][k1 + seg * 8]);
            }
            CP_COMMIT();
            CP_WAIT(1);
        } else {
            CP_WAIT(0);
        }
        __syncthreads();
        if (c < 15) {
            const int k1 = kbase + (c + 1) * 32;
            #pragma unroll
            for (int r = 0; r < 4; ++r) {
                int idx = tid + r * 128;
                wreg[r] = *(const float4*)&W[(size_t)(k1 + (idx >> 4)) * Dn + n0 + (idx & 15) * 4];
            }
        }
        #pragma unroll
        for (int kk = 0; kk < 2; ++kk) {
            uint32_t bh[4], bl[4];
            LDSM_X4T(bh, smem_u32(&Bh[kk * 16 + brow][bcol]));
            LDSM_X4T(bl, smem_u32(&Bl[kk * 16 + brow][bcol]));
            #pragma unroll
            for (int mt = 0; mt < 4; ++mt) {
                uint32_t a[4];
                LDSM_X4(a, smem_u32(&As[buf][mt * 16 + arow][kk * 16 + acol]));
                mma16816(d[mt][0], a, bh[0], bh[1]);
                mma16816(d[mt][1], a, bh[2], bh[3]);
                if (mt < 2) {
                    mma16816(d[mt][0], a, bl[0], bl[1]);
                    mma16816(d[mt][1], a, bl[2], bl[3]);
                }
            }
        }
        __syncthreads();
    }

    float* P = &g_fpart[blockIdx.y][mat][0][0];
    const int g = lane >> 2, cc = (lane & 3) * 2;
    #pragma unroll
    for (int h = 0; h < 2; ++h) {
        #pragma unroll
        for (int j = 0; j < 2; ++j) {
            float v0 = d[h][j][0] + d[h + 2][j][0];
            float v1 = d[h][j][1] + d[h + 2][j][1];
            float v2 = d[h][j][2] + d[h + 2][j][2];
            float v3 = d[h][j][3] + d[h + 2][j][3];
            int r0 = h * 16 + g;
            int col = n0 + nloc + j * 8 + cc;
            *(float2*)&P[r0 * Dn + col] = make_float2(v0, v1);
            *(float2*)&P[(r0 + 8) * Dn + col] = make_float2(v2, v3);
        }
    }
}

// ---------------------------------------------------------------------------
__global__ __launch_bounds__(1024) void lnfinal_fused(
    const float* __restrict__ gamma, const float* __restrict__ beta,
    float* __restrict__ out)
{
    const int row = blockIdx.x;
    const int t = threadIdx.x;
    const int lane = t & 31, wid = t >> 5;
    const float4* fp = (const float4*)&g_fpart[0][0][0][0];

    float4 a = fp[(size_t)(0 * 32 + row) * 1024 + t];
    #pragma unroll
    for (int s = 1; s < 8; ++s) {
        float4 b = fp[(size_t)((s * 2 + 0) * 32 + row) * 1024 + t];
        a.x += b.x; a.y += b.y; a.z += b.z; a.w += b.w;
    }
    float4 stim = make_float4(fmaxf(a.x, 0.f), fmaxf(a.y, 0.f),
                              fmaxf(a.z, 0.f), fmaxf(a.w, 0.f));
    ((float4*)&g_act[0][row * Dn])[t] = stim;

    a = fp[(size_t)(1 * 32 + row) * 1024 + t];
    #pragma unroll
    for (int s = 1; s < 8; ++s) {
        float4 b = fp[(size_t)((s * 2 + 1) * 32 + row) * 1024 + t];
        a.x += b.x; a.y += b.y; a.z += b.z; a.w += b.w;
    }
    float4 rec = make_float4(fmaxf(a.x, 0.f), fmaxf(a.y, 0.f),
                             fmaxf(a.z, 0.f), fmaxf(a.w, 0.f));
    ((float4*)&g_act[1][row * Dn])[t] = rec;

    float s = rec.x + rec.y + rec.z + rec.w;
    float q = rec.x * rec.x + rec.y * rec.y + rec.z * rec.z + rec.w * rec.w;
    #pragma unroll
    for (int off = 16; off > 0; off >>= 1) {
        s += __shfl_down_sync(0xFFFFFFFF, s, off);
        q += __shfl_down_sync(0xFFFFFFFF, q, off);
    }
    __shared__ float rs[32], rq[32], stats[2];
    if (lane == 0) { rs[wid] = s; rq[wid] = q; }
    __syncthreads();
    if (wid == 0) {
        s = rs[lane]; q = rq[lane];
        #pragma unroll
        for (int off = 16; off > 0; off >>= 1) {
            s += __shfl_down_sync(0xFFFFFFFF, s, off);
            q += __shfl_down_sync(0xFFFFFFFF, q, off);
        }
        if (lane == 0) {
            float mean = s * (1.f / Dn);
            float var = q * (1.f / Dn) - mean * mean;
            stats[0] = mean;
            stats[1] = rsqrtf(var + 1e-5f);
        }
    }
    __syncthreads();
    float mean = stats[0], inv = stats[1];
    float4 gm = ((const float4*)gamma)[t];
    float4 bt = ((const float4*)beta)[t];
    float4 o;
    o.x = (rec.x - mean) * inv * gm.x + bt.x + stim.x;
    o.y = (rec.y - mean) * inv * gm.y + bt.y + stim.y;
    o.z = (rec.z - mean) * inv * gm.z + bt.z + stim.z;
    o.w = (rec.w - mean) * inv * gm.w + bt.w + stim.w;
    ((float4*)&out[row * Dn])[t] = o;
}

// ---------------------------------------------------------------------------
__global__ __launch_bounds__(256) void mlp_gemm2(
    const float* __restrict__ X, const float* __restrict__ W, int K, int N, int Kc)
{
    float* __restrict__ P = &g_mp1[0][0][0];
    const int n0 = blockIdx.x * 128;
    const int kbase = blockIdx.y * Kc;
    const int iters = Kc >> 5;

    __shared__ float Xs[32][36];
    __shared__ float Ws[32][128];
    const int tid = threadIdx.x;
    const int xrow = tid >> 3, xk = (tid & 7) << 2;
    const int wk = tid >> 5, wn = (tid & 31) << 2;
    const int tx = tid & 31, ty = tid >> 5;

    float4 xr  = *(const float4*)&X[xrow * K + kbase + xk];
    float4 wr0 = *(const float4*)&W[(size_t)(kbase + wk +  0) * N + n0 + wn];
    float4 wr1 = *(const float4*)&W[(size_t)(kbase + wk +  8) * N + n0 + wn];
    float4 wr2 = *(const float4*)&W[(size_t)(kbase + wk + 16) * N + n0 + wn];
    float4 wr3 = *(const float4*)&W[(size_t)(kbase + wk + 24) * N + n0 + wn];
    float acc[4][4] = {};

    for (int c = 0; c < iters; ++c) {
        Xs[xk + 0][xrow] = xr.x; Xs[xk + 1][xrow] = xr.y;
        Xs[xk + 2][xrow] = xr.z; Xs[xk + 3][xrow] = xr.w;
        *(float4*)&Ws[wk +  0][wn] = wr0;
        *(float4*)&Ws[wk +  8][wn] = wr1;
        *(float4*)&Ws[wk + 16][wn] = wr2;
        *(float4*)&Ws[wk + 24][wn] = wr3;
        __syncthreads();
        if (c + 1 < iters) {
            int k = kbase + (c + 1) * 32;
            xr  = *(const float4*)&X[xrow * K + k + xk];
            wr0 = *(const float4*)&W[(size_t)(k + wk +  0) * N + n0 + wn];
            wr1 = *(const float4*)&W[(size_t)(k + wk +  8) * N + n0 + wn];
            wr2 = *(const float4*)&W[(size_t)(k + wk + 16) * N + n0 + wn];
            wr3 = *(const float4*)&W[(size_t)(k + wk + 24) * N + n0 + wn];
        }
        #pragma unroll 8
        for (int kk = 0; kk < 32; ++kk) {
            float4 a = *(const float4*)&Xs[kk][ty << 2];
            float4 b = *(const float4*)&Ws[kk][tx << 2];
            acc[0][0] = fmaf(a.x, b.x, acc[0][0]); acc[0][1] = fmaf(a.x, b.y, acc[0][1]);
            acc[0][2] = fmaf(a.x, b.z, acc[0][2]); acc[0][3] = fmaf(a.x, b.w, acc[0][3]);
            acc[1][0] = fmaf(a.y, b.x, acc[1][0]); acc[1][1] = fmaf(a.y, b.y, acc[1][1]);
            acc[1][2] = fmaf(a.y, b.z, acc[1][2]); acc[1][3] = fmaf(a.y, b.w, acc[1][3]);
            acc[2][0] = fmaf(a.z, b.x, acc[2][0]); acc[2][1] = fmaf(a.z, b.y, acc[2][1]);
            acc[2][2] = fmaf(a.z, b.z, acc[2][2]); acc[2][3] = fmaf(a.z, b.w, acc[2][3]);
            acc[3][0] = fmaf(a.w, b.x, acc[3][0]); acc[3][1] = fmaf(a.w, b.y, acc[3][1]);
            acc[3][2] = fmaf(a.w, b.z, acc[3][2]); acc[3][3] = fmaf(a.w, b.w, acc[3][3]);
        }
        __syncthreads();
    }
    #pragma unroll
    for (int m = 0; m < 4; ++m) {
        int row = (ty << 2) + m;
        float4 v = make_float4(acc[m][0], acc[m][1], acc[m][2], acc[m][3]);
        *(float4*)&P[((size_t)blockIdx.y * Bn + row) * N + n0 + (tx << 2)] = v;
    }
}

// ---------------------------------------------------------------------------
// Fused tail: fc1 reduce + LN1 + relu + fc2 + LN2 + relu + fc3 + LNo + tanh.
// ---------------------------------------------------------------------------
__global__ __launch_bounds__(256) void mlp_tail(
    const float* __restrict__ fc1_b,
    const float* __restrict__ ln1_g, const float* __restrict__ ln1_b,
    const float* __restrict__ fc2_w, const float* __restrict__ fc2_b,
    const float* __restrict__ ln2_g, const float* __restrict__ ln2_b,
    const float* __restrict__ fc3_w, const float* __restrict__ fc3_b,
    const float* __restrict__ lno_g, const float* __restrict__ lno_b)
{
    const int row = blockIdx.x;
    const int t = threadIdx.x;
    const int lane = t & 31, wid = t >> 5;
    __shared__ float h1s[512], h2s[256], obuf[64];
    __shared__ float rs[8], rq[8], red3[4][64], stats[2];

    // fc1 split-reduce (64 splits), 2 cols/thread
    const float* part = &g_mp1[0][0][0];
    float v1a = fc1_b[t], v1b = fc1_b[t + 256];
    #pragma unroll 4
    for (int sp = 0; sp < 64; ++sp) {
        const float* pr = part + ((size_t)sp * Bn + row) * 512;
        v1a += pr[t];
        v1b += pr[t + 256];
    }
    // LN over 512
    float s = v1a + v1b, q = v1a * v1a + v1b * v1b;
    #pragma unroll
    for (int off = 16; off > 0; off >>= 1) {
        s += __shfl_down_sync(0xFFFFFFFF, s, off);
        q += __shfl_down_sync(0xFFFFFFFF, q, off);
    }
    if (lane == 0) { rs[wid] = s; rq[wid] = q; }
    __syncthreads();
    if (t == 0) {
        float S = 0.f, Q = 0.f;
        #pragma unroll
        for (int w = 0; w < 8; ++w) { S += rs[w]; Q += rq[w]; }
        float mean = S * (1.f / 512);
        stats[0] = mean;
        stats[1] = rsqrtf(Q * (1.f / 512) - mean * mean + 1e-5f);
    }
    __syncthreads();
    h1s[t]       = fmaxf((v1a - stats[0]) * stats[1] * ln1_g[t] + ln1_b[t], 0.f);
    h1s[t + 256] = fmaxf((v1b - stats[0]) * stats[1] * ln1_g[t + 256] + ln1_b[t + 256], 0.f);
    __syncthreads();

    // fc2
    float a0 = 0.f, a1 = 0.f, a2 = 0.f, a3 = 0.f;
    #pragma unroll 4
    for (int k = 0; k < 512; k += 4) {
        a0 = fmaf(h1s[k + 0], fc2_w[(k + 0) * 256 + t], a0);
        a1 = fmaf(h1s[k + 1], fc2_w[(k + 1) * 256 + t], a1);
        a2 = fmaf(h1s[k + 2], fc2_w[(k + 2) * 256 + t], a2);
        a3 = fmaf(h1s[k + 3], fc2_w[(k + 3) * 256 + t], a3);
    }
    float v = fc2_b[t] + (a0 + a1) + (a2 + a3);

    s = v; q = v * v;
    #pragma unroll
    for (int off = 16; off > 0; off >>= 1) {
        s += __shfl_down_sync(0xFFFFFFFF, s, off);
        q += __shfl_down_sync(0xFFFFFFFF, q, off);
    }
    if (lane == 0) { rs[wid] = s; rq[wid] = q; }
    __syncthreads();
    if (t == 0) {
        float S = 0.f, Q = 0.f;
        #pragma unroll
        for (int w = 0; w < 8; ++w) { S += rs[w]; Q += rq[w]; }
        float mean = S * (1.f / 256);
        stats[0] = mean;
        stats[1] = rsqrtf(Q * (1.f / 256) - mean * mean + 1e-5f);
    }
    __syncthreads();
    h2s[t] = fmaxf((v - stats[0]) * stats[1] * ln2_g[t] + ln2_b[t], 0.f);
    __syncthreads();

    // fc3
    {
        int n = t & 63, sl = t >> 6;
        float p = 0.f;
        #pragma unroll 8
        for (int k = sl * 64; k < sl * 64 + 64; ++k)
            p = fmaf(h2s[k], fc3_w[k * 64 + n], p);
        red3[sl][n] = p;
    }
    __syncthreads();
    if (t < 64)
        obuf[t] = fc3_b[t] + (red3[0][t] + red3[1][t]) + (red3[2][t] + red3[3][t]);
    __syncthreads();

    float o = (t < 64) ? obuf[t] : 0.f;
    float s2 = o, q2 = o * o;
    #pragma unroll
    for (int off = 16; off > 0; off >>= 1) {
        s2 += __shfl_down_sync(0xFFFFFFFF, s2, off);
        q2 += __shfl_down_sync(0xFFFFFFFF, q2, off);
    }
    if (lane == 0 && wid < 2) { rs[wid] = s2; rq[wid] = q2; }
    __syncthreads();
    if (t == 0) {
        float S = rs[0] + rs[1], Q = rq[0] + rq[1];
        float mean = S * (1.f / 64);
        stats[0] = mean;
        stats[1] = rsqrtf(Q * (1.f / 64) - mean * mean + 1e-5f);
    }
    __syncthreads();
    if (t < 64)
        g_o[row * 64 + t] = tanhf((o - stats[0]) * stats[1] * lno_g[t] + lno_b[t]);
}

// ---------------------------------------------------------------------------
__global__ __launch_bounds__(256) void csp_alpha()
{
    const int mat = blockIdx.y;
    const int base = blockIdx.x * 256;
    const int ub = (base & 4095) >> 6;
    __shared__ float dsh[4];
    const int t = threadIdx.x;
    if (t < 128) {
        int w = t >> 5, b = t & 31;
        float v = g_o[b * Un + ub + w];
        #pragma unroll
        for (int off = 16; off > 0; off >>= 1)
            v += __shfl_down_sync(0xFFFFFFFF, v, off);
        if (b == 0) dsh[w] = v * (9.9f / (float)Bn);
    }
    __syncthreads();
    int idx = base + t;
    int b = idx >> 12, d = idx & 4095;
    float y = g_act[mat][idx] * dsh[(d >> 6) - ub];
    __nv_bfloat16 hi = __float2bfloat16(y);
    __nv_bfloat16 lo = __float2bfloat16(y - __bfloat162float(hi));
    g_csp[mat][b][d] = hi;
    g_csp[mat][b + 32][d] = lo;
}

// ---------------------------------------------------------------------------
__device__ __forceinline__ void tile_ualpha2(
    int mat, int i0, int j0, int wi, int wj, int lane, float d[8][4],
    __nv_bfloat16 (*Asm)[72], __nv_bfloat16 (*Csm)[136])
{
    const int tid = (wj * 4 + wi) * 32 + lane;
    #pragma unroll
    for (int r = 0; r < 2; ++r) {
        int idx = tid + r * 256;
        int row = idx >> 3, c8 = (idx & 7) * 8;
        *(uint4*)&Asm[row][c8] = *(const uint4*)&g_xsp[mat][row][i0 + c8];
    }
    #pragma unroll
    for (int r = 0; r < 4; ++r) {
        int idx = tid + r * 256;
        int row = idx >> 4, c8 = (idx & 15) * 8;
        *(uint4*)&Csm[row][c8] = *(const uint4*)&g_csp[mat][row][j0 + c8];
    }
    __syncthreads();

    const int arow = (lane & 7) + ((lane & 16) ? 8 : 0);
    const int acol = wi * 16 + ((lane & 8) ? 8 : 0);
    const int brow = (lane & 7) + ((lane & 8) ? 8 : 0);
    const int bcol = wj * 64 + ((lane & 16) ? 8 : 0);

    const int ak[6] = {0, 16, 0, 16, 32, 48};
    const int ck[6] = {0, 16, 32, 48, 0, 16};
    #pragma unroll
    for (int s = 0; s < 6; ++s) {
        uint32_t a[4];
        LDSM_X4T(a, smem_u32(&Asm[ak[s] + arow][acol]));
        #pragma unroll
        for (int n2 = 0; n2 < 4; ++n2) {
            uint32_t b[4];
            LDSM_X4T(b, smem_u32(&Csm[ck[s] + brow][bcol + n2 * 16]));
            mma16816(d[n2 * 2], a, b[0], b[1]);
            mma16816(d[n2 * 2 + 1], a, b[2], b[3]);
        }
    }
}

// ---------------------------------------------------------------------------
__global__ __launch_bounds__(256) void norm_mma(
    const float* __restrict__ Wh, const float* __restrict__ Wr)
{
    const int mat = blockIdx.z;
    const float* __restrict__ W = mat ? Wr : Wh;
    const int i0 = blockIdx.y * 64, j0 = blockIdx.x * 128;
    __shared__ __nv_bfloat16 Asm[64][72];
    __shared__ __nv_bfloat16 Csm[64][136];
    const int lane = threadIdx.x & 31, wid = threadIdx.x >> 5;
    const int wi = wid & 3, wj = wid >> 2;

    float d[8][4] = {};
    tile_ualpha2(mat, i0, j0, wi, wj, lane, d, Asm, Csm);

    const int g = lane >> 2, cc = (lane & 3) * 2;
    const int i = i0 + wi * 16 + g;
    float s0 = 0.f, s1 = 0.f;
    #pragma unroll
    for (int nf = 0; nf < 8; ++nf) {
        int j = j0 + wj * 64 + nf * 8 + cc;
        float2 w0 = *(const float2*)&W[(size_t)i * Dn + j];
        float2 w1 = *(const float2*)&W[(size_t)(i + 8) * Dn + j];
        float v;
        v = w0.x + d[nf][0]; s0 = fmaf(v, v, s0);
        v = w0.y + d[nf][1]; s0 = fmaf(v, v, s0);
        v = w1.x + d[nf][2]; s1 = fmaf(v, v, s1);
        v = w1.y + d[nf][3]; s1 = fmaf(v, v, s1);
    }
    s0 += __shfl_xor_sync(0xFFFFFFFF, s0, 1);
    s0 += __shfl_xor_sync(0xFFFFFFFF, s0, 2);
    s1 += __shfl_xor_sync(0xFFFFFFFF, s1, 1);
    s1 += __shfl_xor_sync(0xFFFFFFFF, s1, 2);
    if ((lane & 3) == 0) {
        g_part[mat][blockIdx.x * 2 + wj][i] = s0;
        g_part[mat][blockIdx.x * 2 + wj][i + 8] = s1;
    }
}

// ---------------------------------------------------------------------------
__global__ __launch_bounds__(256) void sinv_prep()
{
    int idx = blockIdx.x * 256 + threadIdx.x;
    int mat = idx >> 12, i = idx & 4095;
    float s = 0.f;
    #pragma unroll 8
    for (int jb = 0; jb < 64; ++jb) s += g_part[mat][jb][i];
    float dm = g_dm[i];
    g_sinv[mat][i] = dm / fmaxf(dm * sqrtf(s), 1e-12f);
}

// ---------------------------------------------------------------------------
__global__ __launch_bounds__(256) void update_mma(
    const float* __restrict__ Wh, const float* __restrict__ Wr,
    float* __restrict__ out)
{
    const int mat = blockIdx.z;
    const float* __restrict__ W = mat ? Wr : Wh;
    float* __restrict__ O = out + (size_t)(Bn + mat * Dn) * Dn;
    const int i0 = blockIdx.y * 64, j0 = blockIdx.x * 128;
    __shared__ __nv_bfloat16 Asm[64][72];
    __shared__ __nv_bfloat16 Csm[64][136];
    const int lane = threadIdx.x & 31, wid = threadIdx.x >> 5;
    const int wi = wid & 3, wj = wid >> 2;

    float d[8][4] = {};
    tile_ualpha2(mat, i0, j0, wi, wj, lane, d, Asm, Csm);

    const int g = lane >> 2, cc = (lane & 3) * 2;
    const int i = i0 + wi * 16 + g;
    const float sc0 = g_sinv[mat][i];
    const float sc1 = g_sinv[mat][i + 8];
    #pragma unroll
    for (int nf = 0; nf < 8; ++nf) {
        int j = j0 + wj * 64 + nf * 8 + cc;
        float2 w0 = *(const float2*)&W[(size_t)i * Dn + j];
        float2 w1 = *(const float2*)&W[(size_t)(i + 8) * Dn + j];
        float2 v0 = make_float2((w0.x + d[nf][0]) * sc0, (w0.y + d[nf][1]) * sc0);
        float2 v1 = make_float2((w1.x + d[nf][2]) * sc1, (w1.y + d[nf][3]) * sc1);
        *(float2*)&O[(size_t)i * Dn + j] = v0;
        *(float2*)&O[(size_t)(i + 8) * Dn + j] = v1;
    }
}

// ---------------------------------------------------------------------------
extern "C" void kernel_launch(void* const* d_in, const int* in_sizes, int n_in,
                              void* d_out, int out_size)
{
    const float* stimulus = (const float*)d_in[0];
    const float* prev_act = (const float*)d_in[1];
    const float* W_heb    = (const float*)d_in[2];
    const float* W_rec    = (const float*)d_in[3];
    const float* decay    = (const float*)d_in[4];
    const float* ln_rec_g = (const float*)d_in[5];
    const float* ln_rec_b = (const float*)d_in[6];
    const float* fc1_w    = (const float*)d_in[7];
    const float* fc1_b    = (const float*)d_in[8];
    const float* ln1_g    = (const float*)d_in[9];
    const float* ln1_b    = (const float*)d_in[10];
    const float* fc2_w    = (const float*)d_in[11];
    const float* fc2_b    = (const float*)d_in[12];
    const float* ln2_g    = (const float*)d_in[13];
    const float* ln2_b    = (const float*)d_in[14];
    const float* fc3_w    = (const float*)d_in[15];
    const float* fc3_b    = (const float*)d_in[16];
    const float* lno_g    = (const float*)d_in[17];
    const float* lno_b    = (const float*)d_in[18];
    float* out = (float*)d_out;

    prep_all<<<dim3(512, 2), 256>>>(stimulus, prev_act, decay);
    fwd_mma3<<<dim3(64, 8, 2), 128>>>(W_heb, W_rec);
    lnfinal_fused<<<32, 1024>>>(ln_rec_g, ln_rec_b, out);
    mlp_gemm2<<<dim3(4, 64), 256>>>(out, fc1_w, 4096, 512, 64);
    mlp_tail<<<32, 256>>>(fc1_b, ln1_g, ln1_b, fc2_w, fc2_b, ln2_g, ln2_b,
                          fc3_w, fc3_b, lno_g, lno_b);
    csp_alpha<<<dim3(512, 2), 256>>>();
    norm_mma<<<dim3(32, 64, 2), 256>>>(W_heb, W_rec);
    sinv_prep<<<32, 256>>>();
    update_mma<<<dim3(32, 64, 2), 256>>>(W_heb, W_rec, out);
}

// round 17
// speedup vs baseline: 1.0228x; 1.0228x over previous
#include <cuda_runtime.h>
#include <cuda_bf16.h>
#include <math.h>
#include <stdint.h>

#define Dn 4096
#define Bn 32
#define Un 64

__device__ __nv_bfloat16 g_xsp[2][64][Dn];
__device__ __nv_bfloat16 g_csp[2][64][Dn];
__device__ float g_fpart[8][2][Bn][Dn];
__device__ float g_act[2][Bn * Dn];
__device__ float g_mp1[64][Bn][512];
__device__ float g_o[Bn * Un];
__device__ float g_dm[Dn];
__device__ float g_part[2][64][Dn];
__device__ float g_sinv[2][Dn];

__device__ __forceinline__ uint32_t smem_u32(const void* p) {
    uint32_t a;
    asm("{ .reg .u64 t; cvta.to.shared.u64 t, %1; cvt.u32.u64 %0, t; }" : "=r"(a) : "l"(p));
    return a;
}
__device__ __forceinline__ void cvt2(float f0, float f1, uint32_t& h, uint32_t& l) {
    asm("cvt.rn.bf16x2.f32 %0, %1, %2;" : "=r"(h) : "f"(f1), "f"(f0));
    float g0 = __uint_as_float(h << 16);
    float g1 = __uint_as_float(h & 0xFFFF0000u);
    asm("cvt.rn.bf16x2.f32 %0, %1, %2;" : "=r"(l) : "f"(f1 - g1), "f"(f0 - g0));
}
__device__ __forceinline__ void mma16816(float* d, const uint32_t* a,
                                         uint32_t b0, uint32_t b1) {
    asm volatile(
        "mma.sync.aligned.m16n8k16.row.col.f32.bf16.bf16.f32 "
        "{%0,%1,%2,%3}, {%4,%5,%6,%7}, {%8,%9}, {%0,%1,%2,%3};"
        : "+f"(d[0]), "+f"(d[1]), "+f"(d[2]), "+f"(d[3])
        : "r"(a[0]), "r"(a[1]), "r"(a[2]), "r"(a[3]), "r"(b0), "r"(b1));
}
#define LDSM_X4(r, p) \
    asm volatile("ldmatrix.sync.aligned.m8n8.x4.shared.b16 {%0,%1,%2,%3}, [%4];" \
        : "=r"((r)[0]), "=r"((r)[1]), "=r"((r)[2]), "=r"((r)[3]) : "r"(p))
#define LDSM_X4T(r, p) \
    asm volatile("ldmatrix.sync.aligned.m8n8.x4.trans.shared.b16 {%0,%1,%2,%3}, [%4];" \
        : "=r"((r)[0]), "=r"((r)[1]), "=r"((r)[2]), "=r"((r)[3]) : "r"(p))
#define CP_ASYNC16(dst, src) \
    asm volatile("cp.async.ca.shared.global [%0], [%1], 16;" :: "r"(dst), "l"(src))
#define CP_COMMIT() asm volatile("cp.async.commit_group;" ::: "memory")
#define CP_WAIT(n)  asm volatile("cp.async.wait_group %0;" :: "n"(n) : "memory")

// ---------------------------------------------------------------------------
__global__ __launch_bounds__(256) void prep_all(
    const float* __restrict__ stim, const float* __restrict__ prev,
    const float* __restrict__ decay)
{
    int mat = blockIdx.y;
    const float* X = mat ? prev : stim;
    int idx = blockIdx.x * 256 + threadIdx.x;
    float x = X[idx];
    __nv_bfloat16 hi = __float2bfloat16(x);
    __nv_bfloat16 lo = __float2bfloat16(x - __bfloat162float(hi));
    int b = idx >> 12, d = idx & 4095;
    g_xsp[mat][b][d] = hi;
    g_xsp[mat][b + 32][d] = lo;
    if (mat == 0 && idx < Dn) g_dm[idx] = 1.0f - decay[idx];
}

// ---------------------------------------------------------------------------
// fwd v4: W tile fp32 via cp.async; B fragments built in-register
// (4 scalar LDS + 2 cvt2 per (kk, n-half); R5-validated lane mapping).
// 6-MMA hi/lo scheme, split-K 8.
// ---------------------------------------------------------------------------
__global__ __launch_bounds__(128) void fwd_mma4(
    const float* __restrict__ Wh, const float* __restrict__ Wr)
{
    const int mat = blockIdx.z;
    const float* __restrict__ W = mat ? Wr : Wh;
    const int n0 = blockIdx.x * 64;
    const int kbase = blockIdx.y * 512;

    __shared__ __nv_bfloat16 As[2][64][40];
    __shared__ float Ws[2][32][68];

    const int tid = threadIdx.x;
    const int lane = tid & 31;
    const int wid = tid >> 5;
    const int nloc = wid << 4;

    const int lsub = lane >> 3;
    const int arow = (lane & 7) + ((lsub & 1) << 3);
    const int acol = (lsub & 2) << 2;

    const int ar0 = tid >> 1;
    const int as0 = (tid & 1) << 1;

    const int bk = (lane & 3) * 2;        // B fragment k-pair base
    const int bn = lane >> 2;             // B fragment n within 8-wide group

    float d[4][2][4] = {};

    // prologue: A0 + W0
    {
        #pragma unroll
        for (int r = 0; r < 2; ++r) {
            int seg = as0 + r;
            CP_ASYNC16(smem_u32(&As[0][ar0][seg * 8]),
                       (const void*)&g_xsp[mat][ar0][kbase + seg * 8]);
        }
        #pragma unroll
        for (int r = 0; r < 4; ++r) {
            int idx = tid + r * 128;
            int row = idx >> 4, col = (idx & 15) * 4;
            CP_ASYNC16(smem_u32(&Ws[0][row][col]),
                       (const void*)&W[(size_t)(kbase + row) * Dn + n0 + col]);
        }
        CP_COMMIT();
    }

    for (int c = 0; c < 16; ++c) {
        const int buf = c & 1;
        if (c < 15) {
            const int k1 = kbase + (c + 1) * 32;
            #pragma unroll
            for (int r = 0; r < 2; ++r) {
                int seg = as0 + r;
                CP_ASYNC16(smem_u32(&As[buf ^ 1][ar0][seg * 8]),
                           (const void*)&g_xsp[mat][ar0][k1 + seg * 8]);
            }
            #pragma unroll
            for (int r = 0; r < 4; ++r) {
                int idx = tid + r * 128;
                int row = idx >> 4, col = (idx & 15) * 4;
                CP_ASYNC16(smem_u32(&Ws[buf ^ 1][row][col]),
                           (const void*)&W[(size_t)(k1 + row) * Dn + n0 + col]);
            }
            CP_COMMIT();
            CP_WAIT(1);
        } else {
            CP_WAIT(0);
        }
        __syncthreads();

        #pragma unroll
        for (int kk = 0; kk < 2; ++kk) {
            const int k0 = kk * 16 + bk;
            uint32_t bh[2][2], bl[2][2];
            #pragma unroll
            for (int j = 0; j < 2; ++j) {
                int n = nloc + j * 8 + bn;
                float f0 = Ws[buf][k0][n];
                float f1 = Ws[buf][k0 + 1][n];
                float f2 = Ws[buf][k0 + 8][n];
                float f3 = Ws[buf][k0 + 9][n];
                cvt2(f0, f1, bh[j][0], bl[j][0]);
                cvt2(f2, f3, bh[j][1], bl[j][1]);
            }
            #pragma unroll
            for (int mt = 0; mt < 4; ++mt) {
                uint32_t a[4];
                LDSM_X4(a, smem_u32(&As[buf][mt * 16 + arow][kk * 16 + acol]));
                mma16816(d[mt][0], a, bh[0][0], bh[0][1]);
                mma16816(d[mt][1], a, bh[1][0], bh[1][1]);
                if (mt < 2) {
                    mma16816(d[mt][0], a, bl[0][0], bl[0][1]);
                    mma16816(d[mt][1], a, bl[1][0], bl[1][1]);
                }
            }
        }
        __syncthreads();
    }

    float* P = &g_fpart[blockIdx.y][mat][0][0];
    const int g = lane >> 2, cc = (lane & 3) * 2;
    #pragma unroll
    for (int h = 0; h < 2; ++h) {
        #pragma unroll
        for (int j = 0; j < 2; ++j) {
            float v0 = d[h][j][0] + d[h + 2][j][0];
            float v1 = d[h][j][1] + d[h + 2][j][1];
            float v2 = d[h][j][2] + d[h + 2][j][2];
            float v3 = d[h][j][3] + d[h + 2][j][3];
            int r0 = h * 16 + g;
            int col = n0 + nloc + j * 8 + cc;
            *(float2*)&P[r0 * Dn + col] = make_float2(v0, v1);
            *(float2*)&P[(r0 + 8) * Dn + col] = make_float2(v2, v3);
        }
    }
}

// ---------------------------------------------------------------------------
__global__ __launch_bounds__(1024) void lnfinal_fused(
    const float* __restrict__ gamma, const float* __restrict__ beta,
    float* __restrict__ out)
{
    const int row = blockIdx.x;
    const int t = threadIdx.x;
    const int lane = t & 31, wid = t >> 5;
    const float4* fp = (const float4*)&g_fpart[0][0][0][0];

    float4 a = fp[(size_t)(0 * 32 + row) * 1024 + t];
    #pragma unroll
    for (int s = 1; s < 8; ++s) {
        float4 b = fp[(size_t)((s * 2 + 0) * 32 + row) * 1024 + t];
        a.x += b.x; a.y += b.y; a.z += b.z; a.w += b.w;
    }
    float4 stim = make_float4(fmaxf(a.x, 0.f), fmaxf(a.y, 0.f),
                              fmaxf(a.z, 0.f), fmaxf(a.w, 0.f));
    ((float4*)&g_act[0][row * Dn])[t] = stim;

    a = fp[(size_t)(1 * 32 + row) * 1024 + t];
    #pragma unroll
    for (int s = 1; s < 8; ++s) {
        float4 b = fp[(size_t)((s * 2 + 1) * 32 + row) * 1024 + t];
        a.x += b.x; a.y += b.y; a.z += b.z; a.w += b.w;
    }
    float4 rec = make_float4(fmaxf(a.x, 0.f), fmaxf(a.y, 0.f),
                             fmaxf(a.z, 0.f), fmaxf(a.w, 0.f));
    ((float4*)&g_act[1][row * Dn])[t] = rec;

    float s = rec.x + rec.y + rec.z + rec.w;
    float q = rec.x * rec.x + rec.y * rec.y + rec.z * rec.z + rec.w * rec.w;
    #pragma unroll
    for (int off = 16; off > 0; off >>= 1) {
        s += __shfl_down_sync(0xFFFFFFFF, s, off);
        q += __shfl_down_sync(0xFFFFFFFF, q, off);
    }
    __shared__ float rs[32], rq[32], stats[2];
    if (lane == 0) { rs[wid] = s; rq[wid] = q; }
    __syncthreads();
    if (wid == 0) {
        s = rs[lane]; q = rq[lane];
        #pragma unroll
        for (int off = 16; off > 0; off >>= 1) {
            s += __shfl_down_sync(0xFFFFFFFF, s, off);
            q += __shfl_down_sync(0xFFFFFFFF, q, off);
        }
        if (lane == 0) {
            float mean = s * (1.f / Dn);
            float var = q * (1.f / Dn) - mean * mean;
            stats[0] = mean;
            stats[1] = rsqrtf(var + 1e-5f);
        }
    }
    __syncthreads();
    float mean = stats[0], inv = stats[1];
    float4 gm = ((const float4*)gamma)[t];
    float4 bt = ((const float4*)beta)[t];
    float4 o;
    o.x = (rec.x - mean) * inv * gm.x + bt.x + stim.x;
    o.y = (rec.y - mean) * inv * gm.y + bt.y + stim.y;
    o.z = (rec.z - mean) * inv * gm.z + bt.z + stim.z;
    o.w = (rec.w - mean) * inv * gm.w + bt.w + stim.w;
    ((float4*)&out[row * Dn])[t] = o;
}

// ---------------------------------------------------------------------------
__global__ __launch_bounds__(256) void mlp_gemm2(
    const float* __restrict__ X, const float* __restrict__ W, int K, int N, int Kc)
{
    float* __restrict__ P = &g_mp1[0][0][0];
    const int n0 = blockIdx.x * 128;
    const int kbase = blockIdx.y * Kc;
    const int iters = Kc >> 5;

    __shared__ float Xs[32][36];
    __shared__ float Ws[32][128];
    const int tid = threadIdx.x;
    const int xrow = tid >> 3, xk = (tid & 7) << 2;
    const int wk = tid >> 5, wn = (tid & 31) << 2;
    const int tx = tid & 31, ty = tid >> 5;

    float4 xr  = *(const float4*)&X[xrow * K + kbase + xk];
    float4 wr0 = *(const float4*)&W[(size_t)(kbase + wk +  0) * N + n0 + wn];
    float4 wr1 = *(const float4*)&W[(size_t)(kbase + wk +  8) * N + n0 + wn];
    float4 wr2 = *(const float4*)&W[(size_t)(kbase + wk + 16) * N + n0 + wn];
    float4 wr3 = *(const float4*)&W[(size_t)(kbase + wk + 24) * N + n0 + wn];
    float acc[4][4] = {};

    for (int c = 0; c < iters; ++c) {
        Xs[xk + 0][xrow] = xr.x; Xs[xk + 1][xrow] = xr.y;
        Xs[xk + 2][xrow] = xr.z; Xs[xk + 3][xrow] = xr.w;
        *(float4*)&Ws[wk +  0][wn] = wr0;
        *(float4*)&Ws[wk +  8][wn] = wr1;
        *(float4*)&Ws[wk + 16][wn] = wr2;
        *(float4*)&Ws[wk + 24][wn] = wr3;
        __syncthreads();
        if (c + 1 < iters) {
            int k = kbase + (c + 1) * 32;
            xr  = *(const float4*)&X[xrow * K + k + xk];
            wr0 = *(const float4*)&W[(size_t)(k + wk +  0) * N + n0 + wn];
            wr1 = *(const float4*)&W[(size_t)(k + wk +  8) * N + n0 + wn];
            wr2 = *(const float4*)&W[(size_t)(k + wk + 16) * N + n0 + wn];
            wr3 = *(const float4*)&W[(size_t)(k + wk + 24) * N + n0 + wn];
        }
        #pragma unroll 8
        for (int kk = 0; kk < 32; ++kk) {
            float4 a = *(const float4*)&Xs[kk][ty << 2];
            float4 b = *(const float4*)&Ws[kk][tx << 2];
            acc[0][0] = fmaf(a.x, b.x, acc[0][0]); acc[0][1] = fmaf(a.x, b.y, acc[0][1]);
            acc[0][2] = fmaf(a.x, b.z, acc[0][2]); acc[0][3] = fmaf(a.x, b.w, acc[0][3]);
            acc[1][0] = fmaf(a.y, b.x, acc[1][0]); acc[1][1] = fmaf(a.y, b.y, acc[1][1]);
            acc[1][2] = fmaf(a.y, b.z, acc[1][2]); acc[1][3] = fmaf(a.y, b.w, acc[1][3]);
            acc[2][0] = fmaf(a.z, b.x, acc[2][0]); acc[2][1] = fmaf(a.z, b.y, acc[2][1]);
            acc[2][2] = fmaf(a.z, b.z, acc[2][2]); acc[2][3] = fmaf(a.z, b.w, acc[2][3]);
            acc[3][0] = fmaf(a.w, b.x, acc[3][0]); acc[3][1] = fmaf(a.w, b.y, acc[3][1]);
            acc[3][2] = fmaf(a.w, b.z, acc[3][2]); acc[3][3] = fmaf(a.w, b.w, acc[3][3]);
        }
        __syncthreads();
    }
    #pragma unroll
    for (int m = 0; m < 4; ++m) {
        int row = (ty << 2) + m;
        float4 v = make_float4(acc[m][0], acc[m][1], acc[m][2], acc[m][3]);
        *(float4*)&P[((size_t)blockIdx.y * Bn + row) * N + n0 + (tx << 2)] = v;
    }
}

// ---------------------------------------------------------------------------
__global__ __launch_bounds__(256) void mlp_tail(
    const float* __restrict__ fc1_b,
    const float* __restrict__ ln1_g, const float* __restrict__ ln1_b,
    const float* __restrict__ fc2_w, const float* __restrict__ fc2_b,
    const float* __restrict__ ln2_g, const float* __restrict__ ln2_b,
    const float* __restrict__ fc3_w, const float* __restrict__ fc3_b,
    const float* __restrict__ lno_g, const float* __restrict__ lno_b)
{
    const int row = blockIdx.x;
    const int t = threadIdx.x;
    const int lane = t & 31, wid = t >> 5;
    __shared__ float h1s[512], h2s[256], obuf[64];
    __shared__ float rs[8], rq[8], red3[4][64], stats[2];

    const float* part = &g_mp1[0][0][0];
    float v1a = fc1_b[t], v1b = fc1_b[t + 256];
    #pragma unroll 4
    for (int sp = 0; sp < 64; ++sp) {
        const float* pr = part + ((size_t)sp * Bn + row) * 512;
        v1a += pr[t];
        v1b += pr[t + 256];
    }
    float s = v1a + v1b, q = v1a * v1a + v1b * v1b;
    #pragma unroll
    for (int off = 16; off > 0; off >>= 1) {
        s += __shfl_down_sync(0xFFFFFFFF, s, off);
        q += __shfl_down_sync(0xFFFFFFFF, q, off);
    }
    if (lane == 0) { rs[wid] = s; rq[wid] = q; }
    __syncthreads();
    if (t == 0) {
        float S = 0.f, Q = 0.f;
        #pragma unroll
        for (int w = 0; w < 8; ++w) { S += rs[w]; Q += rq[w]; }
        float mean = S * (1.f / 512);
        stats[0] = mean;
        stats[1] = rsqrtf(Q * (1.f / 512) - mean * mean + 1e-5f);
    }
    __syncthreads();
    h1s[t]       = fmaxf((v1a - stats[0]) * stats[1] * ln1_g[t] + ln1_b[t], 0.f);
    h1s[t + 256] = fmaxf((v1b - stats[0]) * stats[1] * ln1_g[t + 256] + ln1_b[t + 256], 0.f);
    __syncthreads();

    float a0 = 0.f, a1 = 0.f, a2 = 0.f, a3 = 0.f;
    #pragma unroll 4
    for (int k = 0; k < 512; k += 4) {
        a0 = fmaf(h1s[k + 0], fc2_w[(k + 0) * 256 + t], a0);
        a1 = fmaf(h1s[k + 1], fc2_w[(k + 1) * 256 + t], a1);
        a2 = fmaf(h1s[k + 2], fc2_w[(k + 2) * 256 + t], a2);
        a3 = fmaf(h1s[k + 3], fc2_w[(k + 3) * 256 + t], a3);
    }
    float v = fc2_b[t] + (a0 + a1) + (a2 + a3);

    s = v; q = v * v;
    #pragma unroll
    for (int off = 16; off > 0; off >>= 1) {
        s += __shfl_down_sync(0xFFFFFFFF, s, off);
        q += __shfl_down_sync(0xFFFFFFFF, q, off);
    }
    if (lane == 0) { rs[wid] = s; rq[wid] = q; }
    __syncthreads();
    if (t == 0) {
        float S = 0.f, Q = 0.f;
        #pragma unroll
        for (int w = 0; w < 8; ++w) { S += rs[w]; Q += rq[w]; }
        float mean = S * (1.f / 256);
        stats[0] = mean;
        stats[1] = rsqrtf(Q * (1.f / 256) - mean * mean + 1e-5f);
    }
    __syncthreads();
    h2s[t] = fmaxf((v - stats[0]) * stats[1] * ln2_g[t] + ln2_b[t], 0.f);
    __syncthreads();

    {
        int n = t & 63, sl = t >> 6;
        float p = 0.f;
        #pragma unroll 8
        for (int k = sl * 64; k < sl * 64 + 64; ++k)
            p = fmaf(h2s[k], fc3_w[k * 64 + n], p);
        red3[sl][n] = p;
    }
    __syncthreads();
    if (t < 64)
        obuf[t] = fc3_b[t] + (red3[0][t] + red3[1][t]) + (red3[2][t] + red3[3][t]);
    __syncthreads();

    float o = (t < 64) ? obuf[t] : 0.f;
    float s2 = o, q2 = o * o;
    #pragma unroll
    for (int off = 16; off > 0; off >>= 1) {
        s2 += __shfl_down_sync(0xFFFFFFFF, s2, off);
        q2 += __shfl_down_sync(0xFFFFFFFF, q2, off);
    }
    if (lane == 0 && wid < 2) { rs[wid] = s2; rq[wid] = q2; }
    __syncthreads();
    if (t == 0) {
        float S = rs[0] + rs[1], Q = rq[0] + rq[1];
        float mean = S * (1.f / 64);
        stats[0] = mean;
        stats[1] = rsqrtf(Q * (1.f / 64) - mean * mean + 1e-5f);
    }
    __syncthreads();
    if (t < 64)
        g_o[row * 64 + t] = tanhf((o - stats[0]) * stats[1] * lno_g[t] + lno_b[t]);
}

// ---------------------------------------------------------------------------
__global__ __launch_bounds__(256) void csp_alpha()
{
    const int mat = blockIdx.y;
    const int base = blockIdx.x * 256;
    const int ub = (base & 4095) >> 6;
    __shared__ float dsh[4];
    const int t = threadIdx.x;
    if (t < 128) {
        int w = t >> 5, b = t & 31;
        float v = g_o[b * Un + ub + w];
        #pragma unroll
        for (int off = 16; off > 0; off >>= 1)
            v += __shfl_down_sync(0xFFFFFFFF, v, off);
        if (b == 0) dsh[w] = v * (9.9f / (float)Bn);
    }
    __syncthreads();
    int idx = base + t;
    int b = idx >> 12, d = idx & 4095;
    float y = g_act[mat][idx] * dsh[(d >> 6) - ub];
    __nv_bfloat16 hi = __float2bfloat16(y);
    __nv_bfloat16 lo = __float2bfloat16(y - __bfloat162float(hi));
    g_csp[mat][b][d] = hi;
    g_csp[mat][b + 32][d] = lo;
}

// ---------------------------------------------------------------------------
__device__ __forceinline__ void tile_ualpha2(
    int mat, int i0, int j0, int wi, int wj, int lane, float d[8][4],
    __nv_bfloat16 (*Asm)[72], __nv_bfloat16 (*Csm)[136])
{
    const int tid = (wj * 4 + wi) * 32 + lane;
    #pragma unroll
    for (int r = 0; r < 2; ++r) {
        int idx = tid + r * 256;
        int row = idx >> 3, c8 = (idx & 7) * 8;
        *(uint4*)&Asm[row][c8] = *(const uint4*)&g_xsp[mat][row][i0 + c8];
    }
    #pragma unroll
    for (int r = 0; r < 4; ++r) {
        int idx = tid + r * 256;
        int row = idx >> 4, c8 = (idx & 15) * 8;
        *(uint4*)&Csm[row][c8] = *(const uint4*)&g_csp[mat][row][j0 + c8];
    }
    __syncthreads();

    const int arow = (lane & 7) + ((lane & 16) ? 8 : 0);
    const int acol = wi * 16 + ((lane & 8) ? 8 : 0);
    const int brow = (lane & 7) + ((lane & 8) ? 8 : 0);
    const int bcol = wj * 64 + ((lane & 16) ? 8 : 0);

    const int ak[6] = {0, 16, 0, 16, 32, 48};
    const int ck[6] = {0, 16, 32, 48, 0, 16};
    #pragma unroll
    for (int s = 0; s < 6; ++s) {
        uint32_t a[4];
        LDSM_X4T(a, smem_u32(&Asm[ak[s] + arow][acol]));
        #pragma unroll
        for (int n2 = 0; n2 < 4; ++n2) {
            uint32_t b[4];
            LDSM_X4T(b, smem_u32(&Csm[ck[s] + brow][bcol + n2 * 16]));
            mma16816(d[n2 * 2], a, b[0], b[1]);
            mma16816(d[n2 * 2 + 1], a, b[2], b[3]);
        }
    }
}

// ---------------------------------------------------------------------------
__global__ __launch_bounds__(256) void norm_mma(
    const float* __restrict__ Wh, const float* __restrict__ Wr)
{
    const int mat = blockIdx.z;
    const float* __restrict__ W = mat ? Wr : Wh;
    const int i0 = blockIdx.y * 64, j0 = blockIdx.x * 128;
    __shared__ __nv_bfloat16 Asm[64][72];
    __shared__ __nv_bfloat16 Csm[64][136];
    const int lane = threadIdx.x & 31, wid = threadIdx.x >> 5;
    const int wi = wid & 3, wj = wid >> 2;

    float d[8][4] = {};
    tile_ualpha2(mat, i0, j0, wi, wj, lane, d, Asm, Csm);

    const int g = lane >> 2, cc = (lane & 3) * 2;
    const int i = i0 + wi * 16 + g;
    float s0 = 0.f, s1 = 0.f;
    #pragma unroll
    for (int nf = 0; nf < 8; ++nf) {
        int j = j0 + wj * 64 + nf * 8 + cc;
        float2 w0 = *(const float2*)&W[(size_t)i * Dn + j];
        float2 w1 = *(const float2*)&W[(size_t)(i + 8) * Dn + j];
        float v;
        v = w0.x + d[nf][0]; s0 = fmaf(v, v, s0);
        v = w0.y + d[nf][1]; s0 = fmaf(v, v, s0);
        v = w1.x + d[nf][2]; s1 = fmaf(v, v, s1);
        v = w1.y + d[nf][3]; s1 = fmaf(v, v, s1);
    }
    s0 += __shfl_xor_sync(0xFFFFFFFF, s0, 1);
    s0 += __shfl_xor_sync(0xFFFFFFFF, s0, 2);
    s1 += __shfl_xor_sync(0xFFFFFFFF, s1, 1);
    s1 += __shfl_xor_sync(0xFFFFFFFF, s1, 2);
    if ((lane & 3) == 0) {
        g_part[mat][blockIdx.x * 2 + wj][i] = s0;
        g_part[mat][blockIdx.x * 2 + wj][i + 8] = s1;
    }
}

// ---------------------------------------------------------------------------
__global__ __launch_bounds__(256) void sinv_prep()
{
    int idx = blockIdx.x * 256 + threadIdx.x;
    int mat = idx >> 12, i = idx & 4095;
    float s = 0.f;
    #pragma unroll 8
    for (int jb = 0; jb < 64; ++jb) s += g_part[mat][jb][i];
    float dm = g_dm[i];
    g_sinv[mat][i] = dm / fmaxf(dm * sqrtf(s), 1e-12f);
}

// ---------------------------------------------------------------------------
__global__ __launch_bounds__(256) void update_mma(
    const float* __restrict__ Wh, const float* __restrict__ Wr,
    float* __restrict__ out)
{
    const int mat = blockIdx.z;
    const float* __restrict__ W = mat ? Wr : Wh;
    float* __restrict__ O = out + (size_t)(Bn + mat * Dn) * Dn;
    const int i0 = blockIdx.y * 64, j0 = blockIdx.x * 128;
    __shared__ __nv_bfloat16 Asm[64][72];
    __shared__ __nv_bfloat16 Csm[64][136];
    const int lane = threadIdx.x & 31, wid = threadIdx.x >> 5;
    const int wi = wid & 3, wj = wid >> 2;

    float d[8][4] = {};
    tile_ualpha2(mat, i0, j0, wi, wj, lane, d, Asm, Csm);

    const int g = lane >> 2, cc = (lane & 3) * 2;
    const int i = i0 + wi * 16 + g;
    const float sc0 = g_sinv[mat][i];
    const float sc1 = g_sinv[mat][i + 8];
    #pragma unroll
    for (int nf = 0; nf < 8; ++nf) {
        int j = j0 + wj * 64 + nf * 8 + cc;
        float2 w0 = *(const float2*)&W[(size_t)i * Dn + j];
        float2 w1 = *(const float2*)&W[(size_t)(i + 8) * Dn + j];
        float2 v0 = make_float2((w0.x + d[nf][0]) * sc0, (w0.y + d[nf][1]) * sc0);
        float2 v1 = make_float2((w1.x + d[nf][2]) * sc1, (w1.y + d[nf][3]) * sc1);
        *(float2*)&O[(size_t)i * Dn + j] = v0;
        *(float2*)&O[(size_t)(i + 8) * Dn + j] = v1;
    }
}

// ---------------------------------------------------------------------------
extern "C" void kernel_launch(void* const* d_in, const int* in_sizes, int n_in,
                              void* d_out, int out_size)
{
    const float* stimulus = (const float*)d_in[0];
    const float* prev_act = (const float*)d_in[1];
    const float* W_heb    = (const float*)d_in[2];
    const float* W_rec    = (const float*)d_in[3];
    const float* decay    = (const float*)d_in[4];
    const float* ln_rec_g = (const float*)d_in[5];
    const float* ln_rec_b = (const float*)d_in[6];
    const float* fc1_w    = (const float*)d_in[7];
    const float* fc1_b    = (const float*)d_in[8];
    const float* ln1_g    = (const float*)d_in[9];
    const float* ln1_b    = (const float*)d_in[10];
    const float* fc2_w    = (const float*)d_in[11];
    const float* fc2_b    = (const float*)d_in[12];
    const float* ln2_g    = (const float*)d_in[13];
    const float* ln2_b    = (const float*)d_in[14];
    const float* fc3_w    = (const float*)d_in[15];
    const float* fc3_b    = (const float*)d_in[16];
    const float* lno_g    = (const float*)d_in[17];
    const float* lno_b    = (const float*)d_in[18];
    float* out = (float*)d_out;

    prep_all<<<dim3(512, 2), 256>>>(stimulus, prev_act, decay);
    fwd_mma4<<<dim3(64, 8, 2), 128>>>(W_heb, W_rec);
    lnfinal_fused<<<32, 1024>>>(ln_rec_g, ln_rec_b, out);
    mlp_gemm2<<<dim3(4, 64), 256>>>(out, fc1_w, 4096, 512, 64);
    mlp_tail<<<32, 256>>>(fc1_b, ln1_g, ln1_b, fc2_w, fc2_b, ln2_g, ln2_b,
                          fc3_w, fc3_b, lno_g, lno_b);
    csp_alpha<<<dim3(512, 2), 256>>>();
    norm_mma<<<dim3(32, 64, 2), 256>>>(W_heb, W_rec);
    sinv_prep<<<32, 256>>>();
    update_mma<<<dim3(32, 64, 2), 256>>>(W_heb, W_rec, out);
}